// round 12
// baseline (speedup 1.0000x reference)
#include <cuda_runtime.h>
#include <math.h>

#define NMAX 50000
#define EMAX 800000
#define DIN  64
#define DH   256
#define BN_EPS 1e-5f
#define SCAN_CHUNK 1024
#define PADA 36
#define PADB 132

// ---------------- scratch (device globals; no allocation allowed) ----------
__device__ float g_agg[(size_t)NMAX * DIN];   // aggregated xs, tf32-rounded
__device__ float g_xst[(size_t)NMAX * DIN];   // xs, tf32-rounded
__device__ float g_xl [(size_t)NMAX * DH];    // xs@W_lin + b (fp32)
__device__ float g_z  [(size_t)NMAX * DH];    // tanh(...) fp32 (epilogue use)
__device__ float g_zt [(size_t)NMAX * DH];    // tanh(...) tf32-rounded (GEMM A)
__device__ float g_wgcn [DIN * DH];
__device__ float g_wlin [DIN * DH];
__device__ float g_wgate[DH * DH];
__device__ int   g_cnt[NMAX];
__device__ int   g_rowstart[NMAX + 1];
__device__ int   g_fill[NMAX];
__device__ int   g_csr_src[EMAX];
__device__ int   g_blocksum[64];
__device__ float g_dinv[NMAX];
__device__ float g_bnsum[DH];
__device__ float g_bnsq [DH];
__device__ int   g_is64;

// ---------------- helpers ---------------------------------------------------
__device__ __forceinline__ int edge_at(const void* e, long long i, int is64) {
    if (is64) return (int)((const long long*)e)[i];
    return ((const int*)e)[i];
}

__device__ __forceinline__ unsigned f2tf32(float v) {
    unsigned r;
    asm("cvt.rna.tf32.f32 %0, %1;" : "=r"(r) : "f"(v));
    return r;
}
__device__ __forceinline__ float tf32f(float v) { return __uint_as_float(f2tf32(v)); }

__device__ __forceinline__ void mma_tf32(float* c, const unsigned* a, const unsigned* b) {
    asm volatile(
        "mma.sync.aligned.m16n8k8.row.col.f32.tf32.tf32.f32 "
        "{%0,%1,%2,%3}, {%4,%5,%6,%7}, {%8,%9}, {%0,%1,%2,%3};\n"
        : "+f"(c[0]), "+f"(c[1]), "+f"(c[2]), "+f"(c[3])
        : "r"(a[0]), "r"(a[1]), "r"(a[2]), "r"(a[3]), "r"(b[0]), "r"(b[1]));
}

__device__ __forceinline__ unsigned smem_u32(const void* p) {
    unsigned r;
    asm("{ .reg .u64 t; cvta.to.shared.u64 t, %1; cvt.u32.u64 %0, t; }"
        : "=r"(r) : "l"(p));
    return r;
}

__device__ __forceinline__ void cp16(unsigned dst, const void* src, int sz) {
    asm volatile("cp.async.cg.shared.global [%0], [%1], 16, %2;"
                 :: "r"(dst), "l"(src), "r"(sz));
}
#define CP_COMMIT() asm volatile("cp.async.commit_group;")
#define CP_WAIT1()  asm volatile("cp.async.wait_group 1;")
#define CP_WAIT0()  asm volatile("cp.async.wait_group 0;")

// ---------------- init: zero cnt + BN sums; block 0 warp 0 detects width ---
__global__ void k_init2(const int* __restrict__ e, int nwords, int N) {
    int i = blockIdx.x * blockDim.x + threadIdx.x;
    if (blockIdx.x == 0 && threadIdx.x < 32) {
        int lane = threadIdx.x;
        int acc = 0;
        for (int j = 1 + 2 * lane; j < nwords; j += 64) acc |= e[j];
#pragma unroll
        for (int o = 16; o > 0; o >>= 1) acc |= __shfl_down_sync(~0u, acc, o);
        if (lane == 0) g_is64 = (acc == 0) ? 1 : 0;
    }
    if (i < N) g_cnt[i] = 0;
    if (i < DH) { g_bnsum[i] = 0.f; g_bnsq[i] = 0.f; }
}

__global__ void k_count(const void* __restrict__ e, int E) {
    int i = blockIdx.x * blockDim.x + threadIdx.x;
    if (i >= E) return;
    int is64 = g_is64;
    int d = edge_at(e, (long long)E + i, is64);
    atomicAdd(&g_cnt[d], 1);
}

// ---------------- pre-round weights to tf32 ---------------------------------
__global__ void k_cvtw(const float* __restrict__ Wg, const float* __restrict__ Wl,
                       const float* __restrict__ Wgate) {
    int i = blockIdx.x * blockDim.x + threadIdx.x;
    if (i < DIN * DH)          g_wgcn[i]              = tf32f(Wg[i]);
    else if (i < 2 * DIN * DH) g_wlin[i - DIN * DH]   = tf32f(Wl[i - DIN * DH]);
    else if (i < 2 * DIN * DH + DH * DH)
                               g_wgate[i - 2 * DIN * DH] = tf32f(Wgate[i - 2 * DIN * DH]);
}

// ---------------- scan: phase 1 per-chunk sums ------------------------------
__global__ void k_scan_p1(int N) {
    __shared__ int wsum[32];
    int b = blockIdx.x, tid = threadIdx.x;
    int i = b * SCAN_CHUNK + tid;
    int v = (i < N) ? g_cnt[i] : 0;
#pragma unroll
    for (int o = 16; o > 0; o >>= 1) v += __shfl_down_sync(~0u, v, o);
    if ((tid & 31) == 0) wsum[tid >> 5] = v;
    __syncthreads();
    if (tid < 32) {
        int s = wsum[tid];
#pragma unroll
        for (int o = 16; o > 0; o >>= 1) s += __shfl_down_sync(~0u, s, o);
        if (tid == 0) g_blocksum[b] = s;
    }
}

// ---------------- scan: phase 3 (block offset computed in-kernel) -----------
__global__ void k_scan_p3(int nb, int N) {
    __shared__ int wsum[32];
    __shared__ int s_off;
    int b = blockIdx.x, tid = threadIdx.x;
    int lane = tid & 31, wid = tid >> 5;

    if (wid == 0) {
        int v0 = (lane < nb) ? g_blocksum[lane] : 0;
        int v1 = (lane + 32 < nb) ? g_blocksum[lane + 32] : 0;
        int p0 = (lane < b) ? v0 : 0;
        int p1 = (lane + 32 < b) ? v1 : 0;
        int off = p0 + p1;
        int tot = v0 + v1;
#pragma unroll
        for (int o = 16; o > 0; o >>= 1) {
            off += __shfl_down_sync(~0u, off, o);
            tot += __shfl_down_sync(~0u, tot, o);
        }
        if (lane == 0) {
            s_off = off;
            if (b == 0) g_rowstart[N] = tot;
        }
    }
    __syncthreads();

    int i = b * SCAN_CHUNK + tid;
    int v = (i < N) ? g_cnt[i] : 0;
    int x = v;
#pragma unroll
    for (int o = 1; o < 32; o <<= 1) {
        int y = __shfl_up_sync(~0u, x, o);
        if (lane >= o) x += y;
    }
    if (lane == 31) wsum[wid] = x;
    __syncthreads();
    if (wid == 0) {
        int s = wsum[lane];
#pragma unroll
        for (int o = 1; o < 32; o <<= 1) {
            int y = __shfl_up_sync(~0u, s, o);
            if (lane >= o) s += y;
        }
        wsum[lane] = s;
    }
    __syncthreads();
    int excl = s_off + x - v + (wid ? wsum[wid - 1] : 0);
    if (i < N) {
        g_rowstart[i] = excl;
        g_fill[i]     = excl;
        g_dinv[i]     = rsqrtf((float)(v + 1));
    }
}

__global__ void k_fillcsr(const void* __restrict__ e, int E) {
    int i = blockIdx.x * blockDim.x + threadIdx.x;
    if (i >= E) return;
    int is64 = g_is64;
    int s = edge_at(e, i, is64);
    int d = edge_at(e, (long long)E + i, is64);
    int pos = atomicAdd(&g_fill[d], 1);
    g_csr_src[pos] = s;
}

// ---------------- xs aggregation: warp per node; emits tf32 agg + tf32 xs --
__global__ __launch_bounds__(256) void k_gatherx(const float* __restrict__ xs, int N) {
    int warp = (blockIdx.x * blockDim.x + threadIdx.x) >> 5;
    int lane = threadIdx.x & 31;
    if (warp >= N) return;
    int n = warp;
    float di = g_dinv[n];

    float2 raw = ((const float2*)(xs + (size_t)n * DIN))[lane];
    ((float2*)(g_xst + (size_t)n * DIN))[lane] =
        make_float2(tf32f(raw.x), tf32f(raw.y));

    float2 a = make_float2(raw.x * di, raw.y * di);

    int e   = g_rowstart[n];
    int end = g_rowstart[n + 1];

    for (; e + 7 < end; e += 8) {
        int   si[8];
        float wi[8];
        float2 vi[8];
#pragma unroll
        for (int u = 0; u < 8; u++) si[u] = g_csr_src[e + u];
#pragma unroll
        for (int u = 0; u < 8; u++) wi[u] = g_dinv[si[u]];
#pragma unroll
        for (int u = 0; u < 8; u++)
            vi[u] = ((const float2*)(xs + (size_t)si[u] * DIN))[lane];
#pragma unroll
        for (int u = 0; u < 8; u++) {
            a.x = fmaf(vi[u].x, wi[u], a.x);
            a.y = fmaf(vi[u].y, wi[u], a.y);
        }
    }
    for (; e < end; e++) {
        int s = g_csr_src[e];
        float w = g_dinv[s];
        float2 v = ((const float2*)(xs + (size_t)s * DIN))[lane];
        a.x = fmaf(v.x, w, a.x);
        a.y = fmaf(v.y, w, a.y);
    }
    a.x *= di; a.y *= di;
    ((float2*)(g_agg + (size_t)n * DIN))[lane] =
        make_float2(tf32f(a.x), tf32f(a.y));
}

// ============================================================================
// tf32 GEMM with cp.async double buffering. Operands are pre-tf32-rounded.
// A SMEM layout: [m][PADA] (row = 32 k-values + pad); B: [k][PADB].
// ============================================================================

// ---- pass 1: z = blockIdx.z==0: tanh(agg@W_gcn+b) -> g_z (+g_zt tf32)
//              blockIdx.z==1: xst@W_lin + b_lin     -> g_xl
__global__ __launch_bounds__(256) void k_gemm_tf32(
        const float* __restrict__ bias0, const float* __restrict__ bias1, int M) {
    extern __shared__ float sm[];
    float* Asm = sm;                         // 2 * 128 * PADA
    float* Bsm = sm + 2 * 128 * PADA;        // 2 * 32 * PADB
    const int K = DIN, NCH = 2;
    int which = blockIdx.z;
    const float* A = which ? g_xst : g_agg;
    const float* B = which ? g_wlin : g_wgcn;
    const float* bias = which ? bias1 : bias0;

    int tid = threadIdx.x;
    int wid = tid >> 5, lane = tid & 31;
    int g = lane >> 2, tig = lane & 3;
    int warp_m = wid & 1, warp_n = wid >> 1;
    int brow = blockIdx.y * 128, bcol = blockIdx.x * 128;
    unsigned sA = smem_u32(Asm), sB = smem_u32(Bsm);

    float acc[4][4][4];
#pragma unroll
    for (int mt = 0; mt < 4; mt++)
#pragma unroll
        for (int nt = 0; nt < 4; nt++)
#pragma unroll
            for (int r = 0; r < 4; r++) acc[mt][nt][r] = 0.f;

#define FILL_A(ch, buf) do {                                                   \
    _Pragma("unroll")                                                          \
    for (int j = 0; j < 4; j++) {                                              \
        int c = tid + j * 256; int row = c >> 3, off = c & 7;                  \
        int grow = brow + row; int ok = grow < M;                              \
        const float* src = A + (size_t)(ok ? grow : 0) * K + (ch) * 32 + off * 4; \
        unsigned dst = sA + ((buf) * 128 * PADA + row * PADA + off * 4) * 4u;  \
        cp16(dst, src, ok ? 16 : 0);                                           \
    } } while (0)
#define FILL_B(ch, buf) do {                                                   \
    _Pragma("unroll")                                                          \
    for (int j = 0; j < 4; j++) {                                              \
        int c = tid + j * 256; int row = c >> 5, off = c & 31;                 \
        const float* src = B + (size_t)((ch) * 32 + row) * DH + bcol + off * 4;\
        unsigned dst = sB + ((buf) * 32 * PADB + row * PADB + off * 4) * 4u;   \
        cp16(dst, src, 16);                                                    \
    } } while (0)

    FILL_A(0, 0); FILL_B(0, 0);
    CP_COMMIT();
    for (int ch = 0; ch < NCH; ch++) {
        int cb = ch & 1;
        if (ch + 1 < NCH) {
            FILL_A(ch + 1, cb ^ 1); FILL_B(ch + 1, cb ^ 1);
            CP_COMMIT();
            CP_WAIT1();
        } else {
            CP_WAIT0();
        }
        __syncthreads();
        const float* Ab = Asm + cb * 128 * PADA;
        const float* Bb = Bsm + cb * 32 * PADB;
#pragma unroll
        for (int kk = 0; kk < 32; kk += 8) {
            unsigned af[4][4], bf[4][2];
#pragma unroll
            for (int mt = 0; mt < 4; mt++) {
                int mb = warp_m * 64 + mt * 16 + g;
                af[mt][0] = __float_as_uint(Ab[mb * PADA + kk + tig]);
                af[mt][1] = __float_as_uint(Ab[(mb + 8) * PADA + kk + tig]);
                af[mt][2] = __float_as_uint(Ab[mb * PADA + kk + tig + 4]);
                af[mt][3] = __float_as_uint(Ab[(mb + 8) * PADA + kk + tig + 4]);
            }
#pragma unroll
            for (int nt = 0; nt < 4; nt++) {
                int nb2 = warp_n * 32 + nt * 8 + g;
                bf[nt][0] = __float_as_uint(Bb[(kk + tig) * PADB + nb2]);
                bf[nt][1] = __float_as_uint(Bb[(kk + tig + 4) * PADB + nb2]);
            }
#pragma unroll
            for (int mt = 0; mt < 4; mt++)
#pragma unroll
                for (int nt = 0; nt < 4; nt++)
                    mma_tf32(acc[mt][nt], af[mt], bf[nt]);
        }
        __syncthreads();
    }
#undef FILL_A
#undef FILL_B

#pragma unroll
    for (int mt = 0; mt < 4; mt++) {
        int row = brow + warp_m * 64 + mt * 16 + g;
#pragma unroll
        for (int nt = 0; nt < 4; nt++) {
            int col = bcol + warp_n * 32 + nt * 8 + 2 * tig;
            float bx = bias[col], by = bias[col + 1];
#pragma unroll
            for (int half = 0; half < 2; half++) {
                int r = row + half * 8;
                if (r >= M) continue;
                float vx = acc[mt][nt][half * 2]     + bx;
                float vy = acc[mt][nt][half * 2 + 1] + by;
                if (!which) {
                    vx = tanhf(vx); vy = tanhf(vy);
                    *(float2*)(g_z  + (size_t)r * DH + col) = make_float2(vx, vy);
                    *(float2*)(g_zt + (size_t)r * DH + col) =
                        make_float2(tf32f(vx), tf32f(vy));
                } else {
                    *(float2*)(g_xl + (size_t)r * DH + col) = make_float2(vx, vy);
                }
            }
        }
    }
}

// ---- pass 2: gate = zt @ W_gate + fused sigmoid/residual/ReLU + BN ---------
__global__ __launch_bounds__(256) void k_gate_tf32(
        const float* __restrict__ bgate, float* __restrict__ OUT, int M) {
    extern __shared__ float sm[];
    float* Asm = sm;
    float* Bsm = sm + 2 * 128 * PADA;
    float* s_sum = sm + 2 * 128 * PADA + 2 * 32 * PADB;
    float* s_sq  = s_sum + 128;
    const int K = DH, NCH = 8;
    const float* A = g_zt;
    const float* B = g_wgate;

    int tid = threadIdx.x;
    int wid = tid >> 5, lane = tid & 31;
    int g = lane >> 2, tig = lane & 3;
    int warp_m = wid & 1, warp_n = wid >> 1;
    int brow = blockIdx.y * 128, bcol = blockIdx.x * 128;
    unsigned sA = smem_u32(Asm), sB = smem_u32(Bsm);

    if (tid < 128) { s_sum[tid] = 0.f; s_sq[tid] = 0.f; }

    float acc[4][4][4];
#pragma unroll
    for (int mt = 0; mt < 4; mt++)
#pragma unroll
        for (int nt = 0; nt < 4; nt++)
#pragma unroll
            for (int r = 0; r < 4; r++) acc[mt][nt][r] = 0.f;

#define FILL_A(ch, buf) do {                                                   \
    _Pragma("unroll")                                                          \
    for (int j = 0; j < 4; j++) {                                              \
        int c = tid + j * 256; int row = c >> 3, off = c & 7;                  \
        int grow = brow + row; int ok = grow < M;                              \
        const float* src = A + (size_t)(ok ? grow : 0) * K + (ch) * 32 + off * 4; \
        unsigned dst = sA + ((buf) * 128 * PADA + row * PADA + off * 4) * 4u;  \
        cp16(dst, src, ok ? 16 : 0);                                           \
    } } while (0)
#define FILL_B(ch, buf) do {                                                   \
    _Pragma("unroll")                                                          \
    for (int j = 0; j < 4; j++) {                                              \
        int c = tid + j * 256; int row = c >> 5, off = c & 31;                 \
        const float* src = B + (size_t)((ch) * 32 + row) * DH + bcol + off * 4;\
        unsigned dst = sB + ((buf) * 32 * PADB + row * PADB + off * 4) * 4u;   \
        cp16(dst, src, 16);                                                    \
    } } while (0)

    FILL_A(0, 0); FILL_B(0, 0);
    CP_COMMIT();
    for (int ch = 0; ch < NCH; ch++) {
        int cb = ch & 1;
        if (ch + 1 < NCH) {
            FILL_A(ch + 1, cb ^ 1); FILL_B(ch + 1, cb ^ 1);
            CP_COMMIT();
            CP_WAIT1();
        } else {
            CP_WAIT0();
        }
        __syncthreads();
        const float* Ab = Asm + cb * 128 * PADA;
        const float* Bb = Bsm + cb * 32 * PADB;
#pragma unroll
        for (int kk = 0; kk < 32; kk += 8) {
            unsigned af[4][4], bf[4][2];
#pragma unroll
            for (int mt = 0; mt < 4; mt++) {
                int mb = warp_m * 64 + mt * 16 + g;
                af[mt][0] = __float_as_uint(Ab[mb * PADA + kk + tig]);
                af[mt][1] = __float_as_uint(Ab[(mb + 8) * PADA + kk + tig]);
                af[mt][2] = __float_as_uint(Ab[mb * PADA + kk + tig + 4]);
                af[mt][3] = __float_as_uint(Ab[(mb + 8) * PADA + kk + tig + 4]);
            }
#pragma unroll
            for (int nt = 0; nt < 4; nt++) {
                int nb2 = warp_n * 32 + nt * 8 + g;
                bf[nt][0] = __float_as_uint(Bb[(kk + tig) * PADB + nb2]);
                bf[nt][1] = __float_as_uint(Bb[(kk + tig + 4) * PADB + nb2]);
            }
#pragma unroll
            for (int mt = 0; mt < 4; mt++)
#pragma unroll
                for (int nt = 0; nt < 4; nt++)
                    mma_tf32(acc[mt][nt], af[mt], bf[nt]);
        }
        __syncthreads();
    }
#undef FILL_A
#undef FILL_B

    // epilogue: g=sigmoid(acc+bg); out=relu(xl+g*(z-xl)); BN partial sums
    float csum[4][2], csq[4][2];
#pragma unroll
    for (int nt = 0; nt < 4; nt++) {
        csum[nt][0] = 0.f; csum[nt][1] = 0.f;
        csq [nt][0] = 0.f; csq [nt][1] = 0.f;
    }

#pragma unroll
    for (int mt = 0; mt < 4; mt++) {
#pragma unroll
        for (int half = 0; half < 2; half++) {
            int row = brow + warp_m * 64 + mt * 16 + g + half * 8;
            if (row >= M) continue;
#pragma unroll
            for (int nt = 0; nt < 4; nt++) {
                int col = bcol + warp_n * 32 + nt * 8 + 2 * tig;
                const float* zp = g_z  + (size_t)row * DH + col;
                const float* xp = g_xl + (size_t)row * DH + col;
                float*       op = OUT  + (size_t)row * DH + col;
                float2 zv = *(const float2*)zp;
                float2 xv = *(const float2*)xp;
#pragma unroll
                for (int c = 0; c < 2; c++) {
                    float gp = acc[mt][nt][half * 2 + c] + bgate[col + c];
                    float gg = 1.f / (1.f + expf(-gp));
                    float zz = c ? zv.y : zv.x;
                    float xx = c ? xv.y : xv.x;
                    float o = fmaf(gg, zz - xx, xx);
                    o = fmaxf(o, 0.f);
                    op[c] = o;
                    csum[nt][c] += o;
                    csq [nt][c] += o * o;
                }
            }
        }
    }
#pragma unroll
    for (int nt = 0; nt < 4; nt++) {
        int cl = warp_n * 32 + nt * 8 + 2 * tig;
        atomicAdd(&s_sum[cl],     csum[nt][0]);
        atomicAdd(&s_sum[cl + 1], csum[nt][1]);
        atomicAdd(&s_sq [cl],     csq [nt][0]);
        atomicAdd(&s_sq [cl + 1], csq [nt][1]);
    }
    __syncthreads();
    if (tid < 128) {
        atomicAdd(&g_bnsum[bcol + tid], s_sum[tid]);
        atomicAdd(&g_bnsq [bcol + tid], s_sq [tid]);
    }
}

// ---------------- norm (BN stats folded in: per-block recompute) ------------
__global__ __launch_bounds__(256) void k_norm2(float* __restrict__ OUT,
        const float* __restrict__ gamma, const float* __restrict__ beta, int N) {
    __shared__ float s_sc[DH], s_sh[DH];
    int tid = threadIdx.x;
    {
        float invn = 1.0f / (float)N;
        float mu  = g_bnsum[tid] * invn;
        float var = g_bnsq[tid] * invn - mu * mu;
        float sc  = gamma[tid] * rsqrtf(var + BN_EPS);
        s_sc[tid] = sc;
        s_sh[tid] = beta[tid] - mu * sc;
    }
    __syncthreads();
    int i = blockIdx.x * blockDim.x + tid;
    int total = N * (DH / 4);
    if (i >= total) return;
    int c4 = i & 63;
    float4 sc = ((const float4*)s_sc)[c4];
    float4 sh = ((const float4*)s_sh)[c4];
    float4 v = ((float4*)OUT)[i];
    v.x = fmaf(v.x, sc.x, sh.x);
    v.y = fmaf(v.y, sc.y, sh.y);
    v.z = fmaf(v.z, sc.z, sh.z);
    v.w = fmaf(v.w, sc.w, sh.w);
    ((float4*)OUT)[i] = v;
}

// ---------------- launch ----------------------------------------------------
extern "C" void kernel_launch(void* const* d_in, const int* in_sizes, int n_in,
                              void* d_out, int out_size) {
    const float* xs     = (const float*)d_in[0];
    const void*  edges  =               d_in[1];
    const float* W_gcn  = (const float*)d_in[2];
    const float* b_gcn  = (const float*)d_in[3];
    const float* W_lin  = (const float*)d_in[4];
    const float* b_lin  = (const float*)d_in[5];
    const float* W_gate = (const float*)d_in[6];
    const float* b_gate = (const float*)d_in[7];
    const float* gamma  = (const float*)d_in[8];
    const float* beta   = (const float*)d_in[9];
    float* out = (float*)d_out;

    int N = in_sizes[0] / DIN;     // 50000
    int E = in_sizes[1] / 2;       // 800000

    int nwords = 2048;
    if (2 * E < nwords) nwords = 2 * E;

    int nb = (N + SCAN_CHUNK - 1) / SCAN_CHUNK;
    if (nb > 64) nb = 64;          // g_blocksum capacity (N<=65536 here)

    const int SMEM_G = (2 * 128 * PADA + 2 * 32 * PADB) * 4;   // 70656
    const int SMEM_GATE = SMEM_G + 256 * 4;                    // 71680
    cudaFuncSetAttribute(k_gemm_tf32, cudaFuncAttributeMaxDynamicSharedMemorySize, SMEM_G);
    cudaFuncSetAttribute(k_gate_tf32, cudaFuncAttributeMaxDynamicSharedMemorySize, SMEM_GATE);

    k_init2<<<(N + 255) / 256, 256>>>((const int*)edges, nwords, N);
    k_count<<<(E + 255) / 256, 256>>>(edges, E);
    k_scan_p1<<<nb, SCAN_CHUNK>>>(N);
    k_scan_p3<<<nb, SCAN_CHUNK>>>(nb, N);
    k_fillcsr<<<(E + 255) / 256, 256>>>(edges, E);

    k_cvtw<<<(2 * DIN * DH + DH * DH + 255) / 256, 256>>>(W_gcn, W_lin, W_gate);
    k_gatherx<<<(N + 7) / 8, 256>>>(xs, N);

    dim3 g2(2, (N + 127) / 128, 2);
    k_gemm_tf32<<<g2, 256, SMEM_G>>>(b_gcn, b_lin, N);         // -> g_z,g_zt,g_xl

    dim3 g1(2, (N + 127) / 128);
    k_gate_tf32<<<g1, 256, SMEM_GATE>>>(b_gate, out, N);

    k_norm2<<<(N * (DH / 4) + 255) / 256, 256>>>(out, gamma, beta, N);
}

// round 14
// speedup vs baseline: 1.2977x; 1.2977x over previous
#include <cuda_runtime.h>
#include <math.h>

#define NMAX 50000
#define EMAX 800000
#define DIN  64
#define DH   256
#define BN_EPS 1e-5f
#define SCAN_CHUNK 1024
#define PADW 132

// ---------------- scratch (device globals; no allocation allowed) ----------
__device__ float g_agg[(size_t)NMAX * DIN];   // aggregated xs (pre-projection)
__device__ float g_xl [(size_t)NMAX * DH];
__device__ float g_z  [(size_t)NMAX * DH];
__device__ int   g_cnt[NMAX];
__device__ int   g_rowstart[NMAX + 1];
__device__ int   g_fill[NMAX];
__device__ int   g_csr_src[EMAX];
__device__ int   g_blocksum[64];
__device__ float g_dinv[NMAX];
__device__ float g_bnsum[DH];
__device__ float g_bnsq [DH];
__device__ int   g_is64;

// ---------------- helpers ---------------------------------------------------
__device__ __forceinline__ int edge_at(const void* e, long long i, int is64) {
    if (is64) return (int)((const long long*)e)[i];
    return ((const int*)e)[i];
}

__device__ __forceinline__ unsigned f2tf32(float v) {
    unsigned r;
    asm("cvt.rna.tf32.f32 %0, %1;" : "=r"(r) : "f"(v));
    return r;
}

__device__ __forceinline__ void mma_tf32(float* c, const unsigned* a, const unsigned* b) {
    asm volatile(
        "mma.sync.aligned.m16n8k8.row.col.f32.tf32.tf32.f32 "
        "{%0,%1,%2,%3}, {%4,%5,%6,%7}, {%8,%9}, {%0,%1,%2,%3};\n"
        : "+f"(c[0]), "+f"(c[1]), "+f"(c[2]), "+f"(c[3])
        : "r"(a[0]), "r"(a[1]), "r"(a[2]), "r"(a[3]), "r"(b[0]), "r"(b[1]));
}

// ---------------- init: zero cnt + BN sums; block 0 warp 0 detects width ---
// int64 data (values < 2^31) has every odd 32-bit word zero.
__global__ void k_init2(const int* __restrict__ e, int nwords, int N) {
    int i = blockIdx.x * blockDim.x + threadIdx.x;
    if (blockIdx.x == 0 && threadIdx.x < 32) {
        int lane = threadIdx.x;
        int acc = 0;
        for (int j = 1 + 2 * lane; j < nwords; j += 64) acc |= e[j];
#pragma unroll
        for (int o = 16; o > 0; o >>= 1) acc |= __shfl_down_sync(~0u, acc, o);
        if (lane == 0) g_is64 = (acc == 0) ? 1 : 0;
    }
    if (i < N) g_cnt[i] = 0;
    if (i < DH) { g_bnsum[i] = 0.f; g_bnsq[i] = 0.f; }
}

// ---------------- combined: lin-GEMM blocks + edge-count blocks -------------
// Blocks [0, nlin): xl = xs @ W_lin + b_lin   (identical to proven tf32 GEMM)
// Blocks [nlin, ..): degree count atomics.
__global__ __launch_bounds__(256) void k_count_lin(
        const void* __restrict__ edges, int E,
        const float* __restrict__ xs,
        const float* __restrict__ Wl, const float* __restrict__ blin,
        int M, int nlin) {
    __shared__ unsigned As[32][PADW];
    __shared__ unsigned Bs[32][PADW];

    if (blockIdx.x >= nlin) {                  // ---- count path ----
        int i = (blockIdx.x - nlin) * blockDim.x + threadIdx.x;
        if (i >= E) return;
        int is64 = g_is64;
        int d = edge_at(edges, (long long)E + i, is64);
        atomicAdd(&g_cnt[d], 1);
        return;
    }

    // ---- lin GEMM path ----
    const int K = DIN;
    int tid = threadIdx.x;
    int wid = tid >> 5, lane = tid & 31;
    int g = lane >> 2, tig = lane & 3;
    int warp_m = wid & 1, warp_n = wid >> 1;
    int brow = (blockIdx.x >> 1) * 128, bcol = (blockIdx.x & 1) * 128;

    float acc[4][4][4];
#pragma unroll
    for (int mt = 0; mt < 4; mt++)
#pragma unroll
        for (int nt = 0; nt < 4; nt++)
#pragma unroll
            for (int r = 0; r < 4; r++) acc[mt][nt][r] = 0.f;

    for (int k0 = 0; k0 < K; k0 += 32) {
#pragma unroll
        for (int l = 0; l < 4; l++) {
            int s = tid + l * 256;
            int m = s >> 3, kq = s & 7;
            float4 v = make_float4(0.f, 0.f, 0.f, 0.f);
            if (brow + m < M)
                v = *(const float4*)(xs + (size_t)(brow + m) * K + k0 + kq * 4);
            As[kq * 4 + 0][m] = f2tf32(v.x);
            As[kq * 4 + 1][m] = f2tf32(v.y);
            As[kq * 4 + 2][m] = f2tf32(v.z);
            As[kq * 4 + 3][m] = f2tf32(v.w);
        }
#pragma unroll
        for (int l = 0; l < 4; l++) {
            int s = tid + l * 256;
            int k = s >> 5, nq = s & 31;
            float4 v = *(const float4*)(Wl + (size_t)(k0 + k) * DH + bcol + nq * 4);
            Bs[k][nq * 4 + 0] = f2tf32(v.x);
            Bs[k][nq * 4 + 1] = f2tf32(v.y);
            Bs[k][nq * 4 + 2] = f2tf32(v.z);
            Bs[k][nq * 4 + 3] = f2tf32(v.w);
        }
        __syncthreads();
#pragma unroll
        for (int kk = 0; kk < 32; kk += 8) {
            unsigned af[4][4], bf[4][2];
#pragma unroll
            for (int mt = 0; mt < 4; mt++) {
                int mb = warp_m * 64 + mt * 16 + g;
                af[mt][0] = As[kk + tig    ][mb];
                af[mt][1] = As[kk + tig    ][mb + 8];
                af[mt][2] = As[kk + tig + 4][mb];
                af[mt][3] = As[kk + tig + 4][mb + 8];
            }
#pragma unroll
            for (int nt = 0; nt < 4; nt++) {
                int nb = warp_n * 32 + nt * 8 + g;
                bf[nt][0] = Bs[kk + tig    ][nb];
                bf[nt][1] = Bs[kk + tig + 4][nb];
            }
#pragma unroll
            for (int mt = 0; mt < 4; mt++)
#pragma unroll
                for (int nt = 0; nt < 4; nt++)
                    mma_tf32(acc[mt][nt], af[mt], bf[nt]);
        }
        __syncthreads();
    }

#pragma unroll
    for (int mt = 0; mt < 4; mt++) {
        int row = brow + warp_m * 64 + mt * 16 + g;
#pragma unroll
        for (int nt = 0; nt < 4; nt++) {
            int col = bcol + warp_n * 32 + nt * 8 + 2 * tig;
            float bx = blin[col], by = blin[col + 1];
            if (row < M) {
                float2 v = make_float2(acc[mt][nt][0] + bx, acc[mt][nt][1] + by);
                *(float2*)(g_xl + (size_t)row * DH + col) = v;
            }
            if (row + 8 < M) {
                float2 v = make_float2(acc[mt][nt][2] + bx, acc[mt][nt][3] + by);
                *(float2*)(g_xl + (size_t)(row + 8) * DH + col) = v;
            }
        }
    }
}

// ---------------- scan: phase 1 per-chunk sums ------------------------------
__global__ void k_scan_p1(int N) {
    __shared__ int wsum[32];
    int b = blockIdx.x, tid = threadIdx.x;
    int i = b * SCAN_CHUNK + tid;
    int v = (i < N) ? g_cnt[i] : 0;
#pragma unroll
    for (int o = 16; o > 0; o >>= 1) v += __shfl_down_sync(~0u, v, o);
    if ((tid & 31) == 0) wsum[tid >> 5] = v;
    __syncthreads();
    if (tid < 32) {
        int s = wsum[tid];
#pragma unroll
        for (int o = 16; o > 0; o >>= 1) s += __shfl_down_sync(~0u, s, o);
        if (tid == 0) g_blocksum[b] = s;
    }
}

// ---------------- scan: phase 3 (block offset computed in-kernel) -----------
__global__ void k_scan_p3(int nb, int N) {
    __shared__ int wsum[32];
    __shared__ int s_off;
    int b = blockIdx.x, tid = threadIdx.x;
    int lane = tid & 31, wid = tid >> 5;

    if (wid == 0) {
        int v0 = (lane < nb) ? g_blocksum[lane] : 0;
        int v1 = (lane + 32 < nb) ? g_blocksum[lane + 32] : 0;
        int p0 = (lane < b) ? v0 : 0;
        int p1 = (lane + 32 < b) ? v1 : 0;
        int off = p0 + p1;
        int tot = v0 + v1;
#pragma unroll
        for (int o = 16; o > 0; o >>= 1) {
            off += __shfl_down_sync(~0u, off, o);
            tot += __shfl_down_sync(~0u, tot, o);
        }
        if (lane == 0) {
            s_off = off;
            if (b == 0) g_rowstart[N] = tot;
        }
    }
    __syncthreads();

    int i = b * SCAN_CHUNK + tid;
    int v = (i < N) ? g_cnt[i] : 0;
    int x = v;
#pragma unroll
    for (int o = 1; o < 32; o <<= 1) {
        int y = __shfl_up_sync(~0u, x, o);
        if (lane >= o) x += y;
    }
    if (lane == 31) wsum[wid] = x;
    __syncthreads();
    if (wid == 0) {
        int s = wsum[lane];
#pragma unroll
        for (int o = 1; o < 32; o <<= 1) {
            int y = __shfl_up_sync(~0u, s, o);
            if (lane >= o) s += y;
        }
        wsum[lane] = s;
    }
    __syncthreads();
    int excl = s_off + x - v + (wid ? wsum[wid - 1] : 0);
    if (i < N) {
        g_rowstart[i] = excl;
        g_fill[i]     = excl;
        g_dinv[i]     = rsqrtf((float)(v + 1));
    }
}

__global__ void k_fillcsr(const void* __restrict__ e, int E) {
    int i = blockIdx.x * blockDim.x + threadIdx.x;
    if (i >= E) return;
    int is64 = g_is64;
    int s = edge_at(e, i, is64);
    int d = edge_at(e, (long long)E + i, is64);
    int pos = atomicAdd(&g_fill[d], 1);
    g_csr_src[pos] = s;
}

// ---------------- xs aggregation: warp per node, float2 per lane ------------
// agg[n] = dinv[n] * ( dinv[n]*xs[n] + sum_{s in N(n)} dinv[s]*xs[s] )
__global__ __launch_bounds__(256) void k_gatherx(const float* __restrict__ xs, int N) {
    int warp = (blockIdx.x * blockDim.x + threadIdx.x) >> 5;
    int lane = threadIdx.x & 31;
    if (warp >= N) return;
    int n = warp;
    float di = g_dinv[n];

    float2 a = ((const float2*)(xs + (size_t)n * DIN))[lane];
    a.x *= di; a.y *= di;

    int e   = g_rowstart[n];
    int end = g_rowstart[n + 1];

    for (; e + 7 < end; e += 8) {
        int   si[8];
        float wi[8];
        float2 vi[8];
#pragma unroll
        for (int u = 0; u < 8; u++) si[u] = g_csr_src[e + u];
#pragma unroll
        for (int u = 0; u < 8; u++) wi[u] = g_dinv[si[u]];
#pragma unroll
        for (int u = 0; u < 8; u++)
            vi[u] = ((const float2*)(xs + (size_t)si[u] * DIN))[lane];
#pragma unroll
        for (int u = 0; u < 8; u++) {
            a.x = fmaf(vi[u].x, wi[u], a.x);
            a.y = fmaf(vi[u].y, wi[u], a.y);
        }
    }
    for (; e < end; e++) {
        int s = g_csr_src[e];
        float w = g_dinv[s];
        float2 v = ((const float2*)(xs + (size_t)s * DIN))[lane];
        a.x = fmaf(v.x, w, a.x);
        a.y = fmaf(v.y, w, a.y);
    }
    a.x *= di; a.y *= di;
    ((float2*)(g_agg + (size_t)n * DIN))[lane] = a;
}

// ---- z GEMM: z = tanh(agg @ W_gcn + b_gcn) ---------------------------------
__global__ __launch_bounds__(256) void k_gemm_tf32(
        const float* __restrict__ B0, const float* __restrict__ bias0, int M) {
    __shared__ unsigned As[32][PADW];
    __shared__ unsigned Bs[32][PADW];
    const int K = DIN;
    const float* A = g_agg;

    int tid = threadIdx.x;
    int wid = tid >> 5, lane = tid & 31;
    int g = lane >> 2, tig = lane & 3;
    int warp_m = wid & 1, warp_n = wid >> 1;
    int brow = blockIdx.y * 128, bcol = blockIdx.x * 128;

    float acc[4][4][4];
#pragma unroll
    for (int mt = 0; mt < 4; mt++)
#pragma unroll
        for (int nt = 0; nt < 4; nt++)
#pragma unroll
            for (int r = 0; r < 4; r++) acc[mt][nt][r] = 0.f;

    for (int k0 = 0; k0 < K; k0 += 32) {
#pragma unroll
        for (int l = 0; l < 4; l++) {
            int s = tid + l * 256;
            int m = s >> 3, kq = s & 7;
            float4 v = make_float4(0.f, 0.f, 0.f, 0.f);
            if (brow + m < M)
                v = *(const float4*)(A + (size_t)(brow + m) * K + k0 + kq * 4);
            As[kq * 4 + 0][m] = f2tf32(v.x);
            As[kq * 4 + 1][m] = f2tf32(v.y);
            As[kq * 4 + 2][m] = f2tf32(v.z);
            As[kq * 4 + 3][m] = f2tf32(v.w);
        }
#pragma unroll
        for (int l = 0; l < 4; l++) {
            int s = tid + l * 256;
            int k = s >> 5, nq = s & 31;
            float4 v = *(const float4*)(B0 + (size_t)(k0 + k) * DH + bcol + nq * 4);
            Bs[k][nq * 4 + 0] = f2tf32(v.x);
            Bs[k][nq * 4 + 1] = f2tf32(v.y);
            Bs[k][nq * 4 + 2] = f2tf32(v.z);
            Bs[k][nq * 4 + 3] = f2tf32(v.w);
        }
        __syncthreads();
#pragma unroll
        for (int kk = 0; kk < 32; kk += 8) {
            unsigned af[4][4], bf[4][2];
#pragma unroll
            for (int mt = 0; mt < 4; mt++) {
                int mb = warp_m * 64 + mt * 16 + g;
                af[mt][0] = As[kk + tig    ][mb];
                af[mt][1] = As[kk + tig    ][mb + 8];
                af[mt][2] = As[kk + tig + 4][mb];
                af[mt][3] = As[kk + tig + 4][mb + 8];
            }
#pragma unroll
            for (int nt = 0; nt < 4; nt++) {
                int nb = warp_n * 32 + nt * 8 + g;
                bf[nt][0] = Bs[kk + tig    ][nb];
                bf[nt][1] = Bs[kk + tig + 4][nb];
            }
#pragma unroll
            for (int mt = 0; mt < 4; mt++)
#pragma unroll
                for (int nt = 0; nt < 4; nt++)
                    mma_tf32(acc[mt][nt], af[mt], bf[nt]);
        }
        __syncthreads();
    }

#pragma unroll
    for (int mt = 0; mt < 4; mt++) {
        int row = brow + warp_m * 64 + mt * 16 + g;
#pragma unroll
        for (int nt = 0; nt < 4; nt++) {
            int col = bcol + warp_n * 32 + nt * 8 + 2 * tig;
            float bx = bias0[col], by = bias0[col + 1];
            if (row < M) {
                float vx = tanhf(acc[mt][nt][0] + bx);
                float vy = tanhf(acc[mt][nt][1] + by);
                *(float2*)(g_z + (size_t)row * DH + col) = make_float2(vx, vy);
            }
            if (row + 8 < M) {
                float vx = tanhf(acc[mt][nt][2] + bx);
                float vy = tanhf(acc[mt][nt][3] + by);
                *(float2*)(g_z + (size_t)(row + 8) * DH + col) = make_float2(vx, vy);
            }
        }
    }
}

// ---- gate GEMM (z @ W_gate) + fused sigmoid/residual/ReLU + BN -------------
__global__ __launch_bounds__(256) void k_gate_tf32(
        const float* __restrict__ B, const float* __restrict__ bgate,
        float* __restrict__ OUT, int M) {
    __shared__ unsigned As[32][PADW];
    __shared__ unsigned Bs[32][PADW];
    __shared__ float s_sum[128], s_sq[128];
    const int K = DH;
    const float* A = g_z;

    int tid = threadIdx.x;
    int wid = tid >> 5, lane = tid & 31;
    int g = lane >> 2, tig = lane & 3;
    int warp_m = wid & 1, warp_n = wid >> 1;
    int brow = blockIdx.y * 128, bcol = blockIdx.x * 128;

    if (tid < 128) { s_sum[tid] = 0.f; s_sq[tid] = 0.f; }

    float acc[4][4][4];
#pragma unroll
    for (int mt = 0; mt < 4; mt++)
#pragma unroll
        for (int nt = 0; nt < 4; nt++)
#pragma unroll
            for (int r = 0; r < 4; r++) acc[mt][nt][r] = 0.f;

    for (int k0 = 0; k0 < K; k0 += 32) {
#pragma unroll
        for (int l = 0; l < 4; l++) {
            int s = tid + l * 256;
            int m = s >> 3, kq = s & 7;
            float4 v = make_float4(0.f, 0.f, 0.f, 0.f);
            if (brow + m < M)
                v = *(const float4*)(A + (size_t)(brow + m) * K + k0 + kq * 4);
            As[kq * 4 + 0][m] = f2tf32(v.x);
            As[kq * 4 + 1][m] = f2tf32(v.y);
            As[kq * 4 + 2][m] = f2tf32(v.z);
            As[kq * 4 + 3][m] = f2tf32(v.w);
        }
#pragma unroll
        for (int l = 0; l < 4; l++) {
            int s = tid + l * 256;
            int k = s >> 5, nq = s & 31;
            float4 v = *(const float4*)(B + (size_t)(k0 + k) * DH + bcol + nq * 4);
            Bs[k][nq * 4 + 0] = f2tf32(v.x);
            Bs[k][nq * 4 + 1] = f2tf32(v.y);
            Bs[k][nq * 4 + 2] = f2tf32(v.z);
            Bs[k][nq * 4 + 3] = f2tf32(v.w);
        }
        __syncthreads();
#pragma unroll
        for (int kk = 0; kk < 32; kk += 8) {
            unsigned af[4][4], bf[4][2];
#pragma unroll
            for (int mt = 0; mt < 4; mt++) {
                int mb = warp_m * 64 + mt * 16 + g;
                af[mt][0] = As[kk + tig    ][mb];
                af[mt][1] = As[kk + tig    ][mb + 8];
                af[mt][2] = As[kk + tig + 4][mb];
                af[mt][3] = As[kk + tig + 4][mb + 8];
            }
#pragma unroll
            for (int nt = 0; nt < 4; nt++) {
                int nb = warp_n * 32 + nt * 8 + g;
                bf[nt][0] = Bs[kk + tig    ][nb];
                bf[nt][1] = Bs[kk + tig + 4][nb];
            }
#pragma unroll
            for (int mt = 0; mt < 4; mt++)
#pragma unroll
                for (int nt = 0; nt < 4; nt++)
                    mma_tf32(acc[mt][nt], af[mt], bf[nt]);
        }
        __syncthreads();
    }

    // epilogue: g=sigmoid(acc+bg); out=relu(xl+g*(z-xl)); BN partial sums
    float csum[4][2], csq[4][2];
#pragma unroll
    for (int nt = 0; nt < 4; nt++) {
        csum[nt][0] = 0.f; csum[nt][1] = 0.f;
        csq [nt][0] = 0.f; csq [nt][1] = 0.f;
    }

#pragma unroll
    for (int mt = 0; mt < 4; mt++) {
#pragma unroll
        for (int half = 0; half < 2; half++) {
            int row = brow + warp_m * 64 + mt * 16 + g + half * 8;
            if (row >= M) continue;
#pragma unroll
            for (int nt = 0; nt < 4; nt++) {
                int col = bcol + warp_n * 32 + nt * 8 + 2 * tig;
                const float* zp = g_z  + (size_t)row * DH + col;
                const float* xp = g_xl + (size_t)row * DH + col;
                float*       op = OUT  + (size_t)row * DH + col;
                float2 zv = *(const float2*)zp;
                float2 xv = *(const float2*)xp;
#pragma unroll
                for (int c = 0; c < 2; c++) {
                    float gp = acc[mt][nt][half * 2 + c] + bgate[col + c];
                    float gg = 1.f / (1.f + expf(-gp));
                    float zz = c ? zv.y : zv.x;
                    float xx = c ? xv.y : xv.x;
                    float o = fmaf(gg, zz - xx, xx);
                    o = fmaxf(o, 0.f);
                    op[c] = o;
                    csum[nt][c] += o;
                    csq [nt][c] += o * o;
                }
            }
        }
    }
#pragma unroll
    for (int nt = 0; nt < 4; nt++) {
        int cl = warp_n * 32 + nt * 8 + 2 * tig;
        atomicAdd(&s_sum[cl],     csum[nt][0]);
        atomicAdd(&s_sum[cl + 1], csum[nt][1]);
        atomicAdd(&s_sq [cl],     csq [nt][0]);
        atomicAdd(&s_sq [cl + 1], csq [nt][1]);
    }
    __syncthreads();
    if (tid < 128) {
        atomicAdd(&g_bnsum[bcol + tid], s_sum[tid]);
        atomicAdd(&g_bnsq [bcol + tid], s_sq [tid]);
    }
}

// ---------------- norm (BN stats folded in: per-block recompute) ------------
__global__ __launch_bounds__(256) void k_norm2(float* __restrict__ OUT,
        const float* __restrict__ gamma, const float* __restrict__ beta, int N) {
    __shared__ float s_sc[DH], s_sh[DH];
    int tid = threadIdx.x;
    {
        float invn = 1.0f / (float)N;
        float mu  = g_bnsum[tid] * invn;
        float var = g_bnsq[tid] * invn - mu * mu;
        float sc  = gamma[tid] * rsqrtf(var + BN_EPS);
        s_sc[tid] = sc;
        s_sh[tid] = beta[tid] - mu * sc;
    }
    __syncthreads();
    int i = blockIdx.x * blockDim.x + tid;
    int total = N * (DH / 4);
    if (i >= total) return;
    int c4 = i & 63;
    float4 sc = ((const float4*)s_sc)[c4];
    float4 sh = ((const float4*)s_sh)[c4];
    float4 v = ((float4*)OUT)[i];
    v.x = fmaf(v.x, sc.x, sh.x);
    v.y = fmaf(v.y, sc.y, sh.y);
    v.z = fmaf(v.z, sc.z, sh.z);
    v.w = fmaf(v.w, sc.w, sh.w);
    ((float4*)OUT)[i] = v;
}

// ---------------- launch ----------------------------------------------------
extern "C" void kernel_launch(void* const* d_in, const int* in_sizes, int n_in,
                              void* d_out, int out_size) {
    const float* xs     = (const float*)d_in[0];
    const void*  edges  =               d_in[1];
    const float* W_gcn  = (const float*)d_in[2];
    const float* b_gcn  = (const float*)d_in[3];
    const float* W_lin  = (const float*)d_in[4];
    const float* b_lin  = (const float*)d_in[5];
    const float* W_gate = (const float*)d_in[6];
    const float* b_gate = (const float*)d_in[7];
    const float* gamma  = (const float*)d_in[8];
    const float* beta   = (const float*)d_in[9];
    float* out = (float*)d_out;

    int N = in_sizes[0] / DIN;     // 50000
    int E = in_sizes[1] / 2;       // 800000

    int nwords = 2048;
    if (2 * E < nwords) nwords = 2 * E;

    int nb = (N + SCAN_CHUNK - 1) / SCAN_CHUNK;
    if (nb > 64) nb = 64;          // g_blocksum capacity (N<=65536 here)

    k_init2<<<(N + 255) / 256, 256>>>((const int*)edges, nwords, N);

    int nlin = 2 * ((N + 127) / 128);              // lin-GEMM blocks
    int ncnt = (E + 255) / 256;                    // count blocks
    k_count_lin<<<nlin + ncnt, 256>>>(edges, E, xs, W_lin, b_lin, N, nlin);

    k_scan_p1<<<nb, SCAN_CHUNK>>>(N);
    k_scan_p3<<<nb, SCAN_CHUNK>>>(nb, N);
    k_fillcsr<<<(E + 255) / 256, 256>>>(edges, E);

    k_gatherx<<<(N + 7) / 8, 256>>>(xs, N);

    dim3 g1(2, (N + 127) / 128);
    k_gemm_tf32<<<g1, 256>>>(W_gcn, b_gcn, N);     // -> g_z
    k_gate_tf32<<<g1, 256>>>(W_gate, b_gate, out, N);

    k_norm2<<<(N * (DH / 4) + 255) / 256, 256>>>(out, gamma, beta, N);
}